// round 4
// baseline (speedup 1.0000x reference)
#include <cuda_runtime.h>

// Conv2d 3x3, stride 1, pad 1, NCHW fp32.
// x:      [16, 64, 224, 224]
// weight: [128, 64, 3, 3]
// bias:   [128]
// out:    [16, 128, 224, 224]
//
// Implicit GEMM: M = C_OUT = 128, N = 16*224*224 = 802816, K = 64*9 = 576.
// BM=128, BN=128, BK=9 (one input channel per K-step), 256 threads, 8x8 micro-tile.

#define N_IMG  16
#define CI     64
#define CO     128
#define HDIM   224
#define WDIM   224
#define HW     (HDIM * WDIM)        // 50176, divisible by 128
#define KTOT   (CI * 9)             // 576

// Pre-transposed weights: g_wT[k][m] = weight[m][k], k = ci*9 + kh*3 + kw
__device__ float g_wT[KTOT * CO];

__global__ void transpose_w_kernel(const float* __restrict__ w) {
    int idx = blockIdx.x * 256 + threadIdx.x;   // KTOT*CO = 73728 elements
    if (idx < KTOT * CO) {
        int k = idx / CO;
        int m = idx - k * CO;
        g_wT[idx] = w[m * KTOT + k];
    }
}

__global__ __launch_bounds__(256, 2)
void conv_igemm_kernel(const float* __restrict__ x,
                       const float* __restrict__ bias,
                       float* __restrict__ out) {
    __shared__ float As[9][128];   // weights slice: As[r][m]
    __shared__ float Bs[9][128];   // im2col slice:  Bs[r][c]

    const int tid = threadIdx.x;
    const int tx  = tid & 15;      // 0..15 -> n-dim (spatial)
    const int ty  = tid >> 4;      // 0..15 -> m-dim (out channel)

    // Column block: 128 consecutive (h,w) positions inside one image.
    const long l0g   = (long)blockIdx.x * 128;
    const int  n_img = (int)(l0g / HW);
    const int  l0    = (int)(l0g - (long)n_img * HW);
    const int  h0    = l0 / WDIM;
    const int  w0    = l0 - h0 * WDIM;

    float acc[8][8];
#pragma unroll
    for (int i = 0; i < 8; ++i)
#pragma unroll
        for (int j = 0; j < 8; ++j) acc[i][j] = 0.0f;

    const float* xn = x + (long)n_img * CI * HW;

    for (int ci = 0; ci < CI; ++ci) {
        // ---- Load A tile (9x128 weights, coalesced from transposed buffer) ----
        const float* wt = g_wT + ci * 9 * CO;
#pragma unroll
        for (int t = 0; t < 5; ++t) {
            int idx = tid + t * 256;
            if (idx < 9 * 128) {
                ((float*)As)[idx] = wt[idx];
            }
        }

        // ---- Load B tile (9x128 im2col gather with zero padding) ----
        const float* xc = xn + ci * HW;
#pragma unroll
        for (int t = 0; t < 5; ++t) {
            int idx = tid + t * 256;
            if (idx < 9 * 128) {
                int r = idx >> 7;          // 0..8
                int c = idx & 127;         // 0..127
                int kh = r / 3;
                int kw = r - kh * 3;
                int wc = w0 + c;           // < 224 + 128, wraps at most one row
                int h  = h0;
                int wp = wc;
                if (wc >= WDIM) { h = h0 + 1; wp = wc - WDIM; }
                int hi = h + kh - 1;
                int wi = wp + kw - 1;
                float v = 0.0f;
                if ((unsigned)hi < HDIM && (unsigned)wi < WDIM)
                    v = __ldg(xc + hi * WDIM + wi);
                Bs[r][c] = v;
            }
        }
        __syncthreads();

        // ---- 8x8 micro-tile FFMA over BK=9 ----
#pragma unroll
        for (int r = 0; r < 9; ++r) {
            float a[8], b[8];
#pragma unroll
            for (int i = 0; i < 8; ++i) a[i] = As[r][ty * 8 + i];
#pragma unroll
            for (int j = 0; j < 8; ++j) b[j] = Bs[r][tx * 8 + j];
#pragma unroll
            for (int i = 0; i < 8; ++i)
#pragma unroll
                for (int j = 0; j < 8; ++j)
                    acc[i][j] = fmaf(a[i], b[j], acc[i][j]);
        }
        __syncthreads();
    }

    // ---- Epilogue: add bias, vectorized stores (tile never crosses image) ----
#pragma unroll
    for (int i = 0; i < 8; ++i) {
        int m = ty * 8 + i;
        float bv = __ldg(bias + m);
        float* op = out + ((long)n_img * CO + m) * HW + l0 + tx * 8;
        float4 v0 = make_float4(acc[i][0] + bv, acc[i][1] + bv,
                                acc[i][2] + bv, acc[i][3] + bv);
        float4 v1 = make_float4(acc[i][4] + bv, acc[i][5] + bv,
                                acc[i][6] + bv, acc[i][7] + bv);
        reinterpret_cast<float4*>(op)[0] = v0;
        reinterpret_cast<float4*>(op)[1] = v1;
    }
}

extern "C" void kernel_launch(void* const* d_in, const int* in_sizes, int n_in,
                              void* d_out, int out_size) {
    const float* x    = (const float*)d_in[0];
    const float* w    = (const float*)d_in[1];
    const float* bias = (const float*)d_in[2];
    float* out        = (float*)d_out;

    // 1) Transpose weights into k-major layout for coalesced A-tile loads.
    transpose_w_kernel<<<(KTOT * CO + 255) / 256, 256>>>(w);

    // 2) Implicit GEMM conv. 802816 / 128 = 6272 column blocks.
    conv_igemm_kernel<<<(N_IMG * HW) / 128, 256>>>(x, bias, out);
}

// round 6
// speedup vs baseline: 1.5424x; 1.5424x over previous
#include <cuda_runtime.h>
#include <cuda_bf16.h>
#include <cstdint>

// Conv2d 3x3 s1 p1 NCHW fp32 — implicit GEMM on mma.sync bf16 (m16n8k16),
// 3-pass split precision: AhBh + AhBl + AlBh (al*bl dropped, ~2^-16 rel).
// x: [16,64,224,224]  w: [128,64,3,3]  bias: [128]  out: [16,128,224,224]
// GEMM: M=128 (C_out), N=802816 (spatial), K=576 (=64ci*9tap).
// CTA: 128x128 tile, K in 9 blocks of 64. 256 thr = 8 warps (4M x 2N).

#define CI_   64
#define CO_   128
#define HDIM  224
#define WDIM  224
#define HW_   (HDIM*WDIM)          // 50176
#define KTOT  576
#define KBLK  64
#define NBLKS 9
#define BN    128
#define BPI   (HW_/BN)             // 392
#define NCTAS (16*BPI)             // 6272

#define SROW  144                  // padded row stride (bytes) for 64 bf16 rows
#define TILE_B (128*SROW)          // 18432
#define SMEM_TOTAL (4*TILE_B)      // 73728: Ah, Al, Bh, Bl

__device__ __nv_bfloat16 g_wh[CO_*KTOT];
__device__ __nv_bfloat16 g_wl[CO_*KTOT];

static __device__ __forceinline__ uint32_t smem_u32(const void* p) {
    uint32_t a;
    asm("{ .reg .u64 t; cvta.to.shared.u64 t, %1; cvt.u32.u64 %0, t; }" : "=r"(a) : "l"(p));
    return a;
}

static __device__ __forceinline__ void ldsm_x4(uint32_t* r, uint32_t addr) {
    asm volatile("ldmatrix.sync.aligned.m8n8.x4.shared.b16 {%0,%1,%2,%3}, [%4];"
        : "=r"(r[0]), "=r"(r[1]), "=r"(r[2]), "=r"(r[3]) : "r"(addr));
}

static __device__ __forceinline__ void mma16816(float* c, const uint32_t* a, const uint32_t* b) {
    asm volatile(
        "mma.sync.aligned.m16n8k16.row.col.f32.bf16.bf16.f32 "
        "{%0,%1,%2,%3}, {%4,%5,%6,%7}, {%8,%9}, {%0,%1,%2,%3};"
        : "+f"(c[0]), "+f"(c[1]), "+f"(c[2]), "+f"(c[3])
        : "r"(a[0]), "r"(a[1]), "r"(a[2]), "r"(a[3]), "r"(b[0]), "r"(b[1]));
}

// ---------------- prologue: split weights into bf16 hi/lo ----------------
__global__ void conv_prep_w(const float* __restrict__ w) {
    int i = blockIdx.x * 256 + threadIdx.x;
    if (i < CO_ * KTOT) {
        float v = w[i];
        __nv_bfloat16 h = __float2bfloat16(v);
        g_wh[i] = h;
        g_wl[i] = __float2bfloat16(v - __bfloat162float(h));
    }
}

// ---------------- main kernel ----------------
__global__ void __launch_bounds__(256)
conv_mma_kernel(const float* __restrict__ x,
                const float* __restrict__ bias,
                float* __restrict__ out) {
    extern __shared__ char smem[];
    char* tAh = smem;
    char* tAl = smem + TILE_B;
    char* tBh = smem + 2 * TILE_B;
    char* tBl = smem + 3 * TILE_B;
    const uint32_t sAh = smem_u32(tAh), sAl = smem_u32(tAl);
    const uint32_t sBh = smem_u32(tBh), sBl = smem_u32(tBl);

    const int tid = threadIdx.x;
    const int wid = tid >> 5;
    const int lid = tid & 31;
    const int warp_m = wid & 3;       // 4 warps over M (32 rows each)
    const int warp_n = wid >> 2;      // 2 warps over N (64 cols each)

    const int bi    = blockIdx.x;
    const int n_img = bi / BPI;
    const int l0    = (bi - n_img * BPI) * BN;
    const int h0    = l0 / WDIM;
    const int w0    = l0 - h0 * WDIM;
    const float* xn = x + (size_t)n_img * CI_ * HW_;

    float acc[16][4];
#pragma unroll
    for (int i = 0; i < 16; ++i)
#pragma unroll
        for (int j = 0; j < 4; ++j) acc[i][j] = 0.0f;

    // ldmatrix lane decomposition
    const int lm = lid >> 3;          // matrix index 0..3
    const int lr = lid & 7;           // row within matrix

    for (int b = 0; b < NBLKS; ++b) {
        const int k0 = b * KBLK;

        // ---- A tiles: weights hi/lo, row m: 64 bf16 (128B) at stride 144 ----
        {
            const int row = tid >> 1, half = tid & 1;
            const uint4* sh = reinterpret_cast<const uint4*>(&g_wh[row * KTOT + k0 + half * 32]);
            const uint4* sl = reinterpret_cast<const uint4*>(&g_wl[row * KTOT + k0 + half * 32]);
#pragma unroll
            for (int i = 0; i < 4; ++i) {
                int off = row * SROW + half * 64 + i * 16;
                *reinterpret_cast<uint4*>(tAh + off) = sh[i];
                *reinterpret_cast<uint4*>(tAl + off) = sl[i];
            }
        }

        // ---- B tiles: im2col gather, 8 consecutive k per thread-task ----
        // task t: n = t&127 (lanes coalesced over n), octet = t>>7 (8 k values).
#pragma unroll
        for (int it = 0; it < 4; ++it) {
            const int t   = tid + it * 256;
            const int n   = t & 127;
            const int oct = t >> 7;

            int wc = w0 + n, h = h0, wp = wc;
            if (wc >= WDIM) { h = h0 + 1; wp = wc - WDIM; }

            uint16_t hv[8], lv[8];
#pragma unroll
            for (int j = 0; j < 8; ++j) {
                const int k  = k0 + oct * 8 + j;
                const int ci = k / 9;
                const int r  = k - ci * 9;
                const int kh = r / 3;
                const int kw = r - kh * 3;
                const int hi = h + kh - 1;
                const int wi = wp + kw - 1;
                float v = 0.0f;
                if ((unsigned)hi < HDIM && (unsigned)wi < WDIM)
                    v = __ldg(xn + ci * HW_ + hi * WDIM + wi);
                __nv_bfloat16 hb = __float2bfloat16(v);
                hv[j] = __bfloat16_as_ushort(hb);
                lv[j] = __bfloat16_as_ushort(__float2bfloat16(v - __bfloat162float(hb)));
            }
            uint4 ph, pl;
            ph.x = (uint32_t)hv[0] | ((uint32_t)hv[1] << 16);
            ph.y = (uint32_t)hv[2] | ((uint32_t)hv[3] << 16);
            ph.z = (uint32_t)hv[4] | ((uint32_t)hv[5] << 16);
            ph.w = (uint32_t)hv[6] | ((uint32_t)hv[7] << 16);
            pl.x = (uint32_t)lv[0] | ((uint32_t)lv[1] << 16);
            pl.y = (uint32_t)lv[2] | ((uint32_t)lv[3] << 16);
            pl.z = (uint32_t)lv[4] | ((uint32_t)lv[5] << 16);
            pl.w = (uint32_t)lv[6] | ((uint32_t)lv[7] << 16);
            const int off = n * SROW + oct * 16;
            *reinterpret_cast<uint4*>(tBh + off) = ph;
            *reinterpret_cast<uint4*>(tBl + off) = pl;
        }

        __syncthreads();

        // ---- compute: 4 k16-steps, fragments cached, 3 passes ----
#pragma unroll
        for (int ks = 0; ks < 4; ++ks) {
            const int kbyte = ks * 32;

            uint32_t aH[2][4], aL[2][4], bH[8][2], bL[8][2];
#pragma unroll
            for (int mt = 0; mt < 2; ++mt) {
                // matrix i: row_off=(i&1)*8, col_off=(i>>1)*16
                uint32_t aoff = (uint32_t)((warp_m * 32 + mt * 16 + ((lm & 1) << 3) + lr) * SROW
                                           + kbyte + ((lm >> 1) << 4));
                ldsm_x4(aH[mt], sAh + aoff);
                ldsm_x4(aL[mt], sAl + aoff);
            }
#pragma unroll
            for (int p = 0; p < 4; ++p) {
                // matrix i: row_off=(i>>1)*8, col_off=(i&1)*16 -> r0,r1 = tile 2p; r2,r3 = tile 2p+1
                uint32_t boff = (uint32_t)((warp_n * 64 + p * 16 + ((lm >> 1) << 3) + lr) * SROW
                                           + kbyte + ((lm & 1) << 4));
                uint32_t rb[4];
                ldsm_x4(rb, sBh + boff);
                bH[2 * p][0] = rb[0]; bH[2 * p][1] = rb[1];
                bH[2 * p + 1][0] = rb[2]; bH[2 * p + 1][1] = rb[3];
                ldsm_x4(rb, sBl + boff);
                bL[2 * p][0] = rb[0]; bL[2 * p][1] = rb[1];
                bL[2 * p + 1][0] = rb[2]; bL[2 * p + 1][1] = rb[3];
            }

#pragma unroll
            for (int mt = 0; mt < 2; ++mt)
#pragma unroll
                for (int nt = 0; nt < 8; ++nt) {
                    float* c = acc[mt * 8 + nt];
                    mma16816(c, aH[mt], bH[nt]);   // Ah*Bh
                    mma16816(c, aH[mt], bL[nt]);   // Ah*Bl
                    mma16816(c, aL[mt], bH[nt]);   // Al*Bh
                }
        }

        __syncthreads();
    }

    // ---- epilogue: c0/c1 -> (row, col..col+1); c2/c3 -> (row+8, ...) ----
    const int qr = lid >> 2;          // 0..7
    const int qc = lid & 3;           // 0..3
#pragma unroll
    for (int mt = 0; mt < 2; ++mt) {
        const int m0 = warp_m * 32 + mt * 16 + qr;
        const float bv0 = __ldg(bias + m0);
        const float bv1 = __ldg(bias + m0 + 8);
        float* r0 = out + ((size_t)n_img * CO_ + m0) * HW_ + l0;
        float* r1 = r0 + 8 * HW_;
#pragma unroll
        for (int nt = 0; nt < 8; ++nt) {
            const float* c = acc[mt * 8 + nt];
            const int col = warp_n * 64 + nt * 8 + qc * 2;
            float2 v0 = make_float2(c[0] + bv0, c[1] + bv0);
            float2 v1 = make_float2(c[2] + bv1, c[3] + bv1);
            *reinterpret_cast<float2*>(r0 + col) = v0;
            *reinterpret_cast<float2*>(r1 + col) = v1;
        }
    }
}

extern "C" void kernel_launch(void* const* d_in, const int* in_sizes, int n_in,
                              void* d_out, int out_size) {
    const float* x    = (const float*)d_in[0];
    const float* w    = (const float*)d_in[1];
    const float* bias = (const float*)d_in[2];
    float* out        = (float*)d_out;

    cudaFuncSetAttribute(conv_mma_kernel,
                         cudaFuncAttributeMaxDynamicSharedMemorySize, SMEM_TOTAL);

    conv_prep_w<<<(CO_ * KTOT + 255) / 256, 256>>>(w);
    conv_mma_kernel<<<NCTAS, 256, SMEM_TOTAL>>>(x, bias, out);
}